// round 1
// baseline (speedup 1.0000x reference)
#include <cuda_runtime.h>
#include <stdint.h>

#define NBATCH 8
#define NCLS   80
#define ROWS   17328      // A*HW = 3*5776
#define PITCH  17408      // padded row length for transposed scores
#define TOPK   200
#define CAP    2048       // candidate buffer capacity
#define KW     7          // ceil(200/32) words for keep/suppress bitmasks
#define NPIV   6

// Transposed scores scratch: (B, C, PITCH). ~42.5 MB static device array.
__device__ float g_scoresT[NBATCH * NCLS * PITCH];

// ---------------------------------------------------------------------------
// Kernel A: transpose scores (B, ROWS, C) -> (B, C, PITCH)
// ---------------------------------------------------------------------------
__global__ void transpose_kernel(const float* __restrict__ scores) {
    __shared__ float tile[32][33];
    const int bz = blockIdx.z;
    const int r0 = blockIdx.x * 32;   // row (anchor) tile origin
    const int c0 = blockIdx.y * 32;   // col (class) tile origin
    const float* in = scores + (size_t)bz * ROWS * NCLS;
    float* out = g_scoresT + (size_t)bz * NCLS * PITCH;
    const int tx = threadIdx.x;

    #pragma unroll
    for (int u = 0; u < 4; u++) {
        int ty = threadIdx.y + u * 8;
        int r = r0 + ty, c = c0 + tx;
        if (r < ROWS && c < NCLS)
            tile[ty][tx] = in[(size_t)r * NCLS + c];
    }
    __syncthreads();
    #pragma unroll
    for (int u = 0; u < 4; u++) {
        int ty = threadIdx.y + u * 8;
        int cc = c0 + ty, r = r0 + tx;
        if (cc < NCLS && r < ROWS)
            out[(size_t)cc * PITCH + r] = tile[tx][ty];
    }
}

// ---------------------------------------------------------------------------
// Kernel B: one CTA per (batch, class). Threshold + top-200 + greedy NMS.
// ---------------------------------------------------------------------------
__global__ void __launch_bounds__(256) nms_kernel(const float* __restrict__ boxes,
                                                  float* __restrict__ out) {
    const int tid = threadIdx.x;
    const int bc  = blockIdx.x;            // b*80 + c
    const int b   = bc / NCLS;
    const int c   = bc % NCLS;
    const float* col = g_scoresT + (size_t)bc * PITCH;

    __shared__ int s_cnt[NPIV];
    __shared__ int s_num;
    __shared__ unsigned long long keys[CAP];
    __shared__ float bx1[TOPK], by1[TOPK], bx2[TOPK], by2[TOPK], bar[TOPK], bsc[TOPK];
    __shared__ unsigned int sup[TOPK * KW];
    __shared__ unsigned int s_keepw[KW];

    if (tid < NPIV) s_cnt[tid] = 0;
    if (tid == 0) s_num = 0;
    __syncthreads();

    // ---- Pass 1: count candidates above each pivot (single contiguous read)
    int c0 = 0, c1 = 0, c2 = 0, c3 = 0, c4 = 0, c5 = 0;
    for (int i = tid; i < ROWS; i += 256) {
        float v = col[i];
        c0 += (v > 0.98f); c1 += (v > 0.96f); c2 += (v > 0.92f);
        c3 += (v > 0.84f); c4 += (v > 0.68f); c5 += (v > 0.50f);
    }
    atomicAdd(&s_cnt[0], c0); atomicAdd(&s_cnt[1], c1); atomicAdd(&s_cnt[2], c2);
    atomicAdd(&s_cnt[3], c3); atomicAdd(&s_cnt[4], c4); atomicAdd(&s_cnt[5], c5);
    __syncthreads();

    // ---- Choose the largest pivot with count >= min(TOPK, count>0.5)
    const int n05 = s_cnt[NPIV - 1];
    const int target = (n05 < TOPK) ? n05 : TOPK;
    const float pvs[NPIV] = {0.98f, 0.96f, 0.92f, 0.84f, 0.68f, 0.50f};
    float pivot = 0.50f;
    #pragma unroll
    for (int p = NPIV - 1; p >= 0; p--)
        if (s_cnt[p] >= target) pivot = pvs[p];

    // ---- Pass 2: collect candidates (hits L1/L2 from pass 1)
    for (int i = tid; i < ROWS; i += 256) {
        float v = col[i];
        if (v > pivot) {
            int pos = atomicAdd(&s_num, 1);
            if (pos < CAP)
                keys[pos] = ((unsigned long long)__float_as_uint(v) << 32)
                          | (unsigned int)(~i);
        }
    }
    __syncthreads();
    int cnt = s_num; if (cnt > CAP) cnt = CAP;

    // ---- Pad to power of two and bitonic sort descending
    int P = 256; while (P < cnt) P <<= 1;
    for (int i = cnt + tid; i < P; i += 256) keys[i] = 0ull;
    __syncthreads();

    for (int k = 2; k <= P; k <<= 1) {
        for (int j = k >> 1; j > 0; j >>= 1) {
            for (int i = tid; i < P; i += 256) {
                int l = i ^ j;
                if (l > i) {
                    unsigned long long a = keys[i], d = keys[l];
                    bool sw = ((i & k) == 0) ? (a < d) : (a > d);
                    if (sw) { keys[i] = d; keys[l] = a; }
                }
            }
            __syncthreads();
        }
    }

    const int n_top = (cnt < TOPK) ? cnt : TOPK;

    // ---- Gather boxes for the top-200
    for (int k = tid; k < TOPK; k += 256) {
        if (k < n_top) {
            unsigned long long key = keys[k];
            int idx = (int)(~(unsigned int)(key & 0xffffffffull));
            float4 bb = ((const float4*)boxes)[(size_t)b * ROWS + idx];
            bx1[k] = bb.x; by1[k] = bb.y; bx2[k] = bb.z; by2[k] = bb.w;
            bar[k] = (bb.z - bb.x) * (bb.w - bb.y);
            bsc[k] = __uint_as_float((unsigned int)(key >> 32));
        } else {
            bx1[k] = 0.f; by1[k] = 0.f; bx2[k] = 0.f; by2[k] = 0.f;
            bar[k] = 0.f; bsc[k] = 0.f;
        }
    }
    __syncthreads();

    // ---- Suppression bitmask: sup[i][w] bit jj set iff iou(i, w*32+jj) > 0.5, j > i
    for (int t = tid; t < TOPK * KW; t += 256) {
        int i = t / KW, w = t % KW;
        unsigned int m = 0;
        if (i < n_top) {
            float x1 = bx1[i], y1 = by1[i], x2 = bx2[i], y2 = by2[i], ai = bar[i];
            int j0 = w * 32;
            #pragma unroll 8
            for (int jj = 0; jj < 32; jj++) {
                int j = j0 + jj;
                if (j > i && j < n_top) {
                    float xx1 = fmaxf(x1, bx1[j]);
                    float yy1 = fmaxf(y1, by1[j]);
                    float xx2 = fminf(x2, bx2[j]);
                    float yy2 = fminf(y2, by2[j]);
                    float inter = fmaxf(0.f, xx2 - xx1) * fmaxf(0.f, yy2 - yy1);
                    float iou = inter / (ai + bar[j] - inter);
                    if (iou > 0.5f) m |= (1u << jj);
                }
            }
        }
        sup[t] = m;
    }
    __syncthreads();

    // ---- Serial greedy (thread 0, rem[] fully in registers via unrolled outer)
    if (tid == 0) {
        unsigned int rem[KW];
        #pragma unroll
        for (int w = 0; w < KW; w++) rem[w] = 0u;
        #pragma unroll
        for (int w0 = 0; w0 < KW; w0++) {
            int ibase = w0 * 32;
            for (int ii = 0; ii < 32; ii++) {
                int i = ibase + ii;
                if (i >= n_top) break;
                if (((rem[w0] >> ii) & 1u) == 0u) {
                    #pragma unroll
                    for (int w = 0; w < KW; w++) rem[w] |= sup[i * KW + w];
                }
            }
        }
        #pragma unroll
        for (int w = 0; w < KW; w++) s_keepw[w] = ~rem[w];
    }
    __syncthreads();

    // ---- Write output: (b, c, k, 6) = [x1,y1,x2,y2,score,class] or zeros
    float* o = out + (size_t)bc * (TOPK * 6);
    const float cls = (float)c;
    for (int t = tid; t < TOPK * 6; t += 256) {
        int k = t / 6, f = t % 6;
        bool kp = (k < n_top) && (((s_keepw[k >> 5] >> (k & 31)) & 1u) != 0u);
        float v = 0.f;
        if (kp) {
            switch (f) {
                case 0: v = bx1[k]; break;
                case 1: v = by1[k]; break;
                case 2: v = bx2[k]; break;
                case 3: v = by2[k]; break;
                case 4: v = bsc[k]; break;
                default: v = cls;   break;
            }
        }
        o[t] = v;
    }
}

// ---------------------------------------------------------------------------
extern "C" void kernel_launch(void* const* d_in, const int* in_sizes, int n_in,
                              void* d_out, int out_size) {
    const float* boxes  = (const float*)d_in[0];
    const float* scores = (const float*)d_in[1];
    if (n_in >= 2 && in_sizes[0] > in_sizes[1]) {  // scores is the bigger tensor
        boxes  = (const float*)d_in[1];
        scores = (const float*)d_in[0];
    }
    float* out = (float*)d_out;

    dim3 tgrid((ROWS + 31) / 32, (NCLS + 31) / 32, NBATCH);
    dim3 tblk(32, 8);
    transpose_kernel<<<tgrid, tblk>>>(scores);

    nms_kernel<<<NBATCH * NCLS, 256>>>(boxes, out);
}

// round 2
// speedup vs baseline: 1.4964x; 1.4964x over previous
#include <cuda_runtime.h>
#include <stdint.h>

#define NBATCH 8
#define NCLS   80
#define ROWS   17328      // A*HW = 3*5776
#define ROWS4  4332       // ROWS/4
#define PITCH  17408      // padded row length for transposed scores
#define TOPK   200
#define CAP    1024       // candidate buffer capacity
#define KW     7          // ceil(200/32) words for keep/suppress bitmasks
#define NPIV   6

// Transposed scores scratch: (B, C, PITCH). ~42.5 MB static device array.
__device__ float g_scoresT[NBATCH * NCLS * PITCH];

// ---------------------------------------------------------------------------
// Kernel A: transpose scores (B, ROWS, C) -> (B, C, PITCH)
// ---------------------------------------------------------------------------
__global__ void transpose_kernel(const float* __restrict__ scores) {
    __shared__ float tile[32][33];
    const int bz = blockIdx.z;
    const int r0 = blockIdx.x * 32;   // row (anchor) tile origin
    const int c0 = blockIdx.y * 32;   // col (class) tile origin
    const float* in = scores + (size_t)bz * ROWS * NCLS;
    float* out = g_scoresT + (size_t)bz * NCLS * PITCH;
    const int tx = threadIdx.x;

    #pragma unroll
    for (int u = 0; u < 4; u++) {
        int ty = threadIdx.y + u * 8;
        int r = r0 + ty, c = c0 + tx;
        if (r < ROWS && c < NCLS)
            tile[ty][tx] = in[(size_t)r * NCLS + c];
    }
    __syncthreads();
    #pragma unroll
    for (int u = 0; u < 4; u++) {
        int ty = threadIdx.y + u * 8;
        int cc = c0 + ty, r = r0 + tx;
        if (cc < NCLS && r < ROWS)
            out[(size_t)cc * PITCH + r] = tile[tx][ty];
    }
}

// ---------------------------------------------------------------------------
// Kernel B: one CTA per (batch, class). Threshold + top-200 + greedy NMS.
// ---------------------------------------------------------------------------
__global__ void __launch_bounds__(256) nms_kernel(const float* __restrict__ boxes,
                                                  float* __restrict__ out) {
    const int tid = threadIdx.x;
    const int bc  = blockIdx.x;            // b*80 + c
    const int b   = bc / NCLS;
    const int c   = bc % NCLS;
    const float4* col4 = (const float4*)(g_scoresT + (size_t)bc * PITCH);

    __shared__ int s_cnt[NPIV];
    __shared__ int s_num;
    __shared__ unsigned long long keys[CAP];
    __shared__ float4 s_box4[TOPK];
    __shared__ float s_area[TOPK], s_sc[TOPK];
    __shared__ unsigned int sup[TOPK * KW];
    __shared__ unsigned int s_keepw[KW];

    if (tid < NPIV) s_cnt[tid] = 0;
    if (tid == 0) s_num = 0;
    __syncthreads();

    // ---- Pass 1: count candidates above each pivot (single contiguous read)
    int c0 = 0, c1 = 0, c2 = 0, c3 = 0, c4 = 0, c5 = 0;
    for (int i = tid; i < ROWS4; i += 256) {
        float4 v4 = col4[i];
        float vv[4] = {v4.x, v4.y, v4.z, v4.w};
        #pragma unroll
        for (int u = 0; u < 4; u++) {
            float v = vv[u];
            c0 += (v > 0.98f); c1 += (v > 0.96f); c2 += (v > 0.92f);
            c3 += (v > 0.84f); c4 += (v > 0.68f); c5 += (v > 0.50f);
        }
    }
    atomicAdd(&s_cnt[0], c0); atomicAdd(&s_cnt[1], c1); atomicAdd(&s_cnt[2], c2);
    atomicAdd(&s_cnt[3], c3); atomicAdd(&s_cnt[4], c4); atomicAdd(&s_cnt[5], c5);
    __syncthreads();

    // ---- Choose the largest pivot with count >= min(TOPK, count>0.5)
    const int n05 = s_cnt[NPIV - 1];
    const int target = (n05 < TOPK) ? n05 : TOPK;
    const float pvs[NPIV] = {0.98f, 0.96f, 0.92f, 0.84f, 0.68f, 0.50f};
    float pivot = 0.50f;
    #pragma unroll
    for (int p = NPIV - 1; p >= 0; p--)
        if (s_cnt[p] >= target) pivot = pvs[p];

    // ---- Pass 2: collect candidates (hits L1/L2 from pass 1)
    for (int i = tid; i < ROWS4; i += 256) {
        float4 v4 = col4[i];
        float vv[4] = {v4.x, v4.y, v4.z, v4.w};
        #pragma unroll
        for (int u = 0; u < 4; u++) {
            float v = vv[u];
            if (v > pivot) {
                int pos = atomicAdd(&s_num, 1);
                if (pos < CAP)
                    keys[pos] = ((unsigned long long)__float_as_uint(v) << 32)
                              | (unsigned int)(~(i * 4 + u));
            }
        }
    }
    __syncthreads();
    int cnt = s_num; if (cnt > CAP) cnt = CAP;

    // ---- Pad to power of two and bitonic sort descending
    int P = 256; while (P < cnt) P <<= 1;
    for (int i = cnt + tid; i < P; i += 256) keys[i] = 0ull;
    __syncthreads();

    for (int k = 2; k <= P; k <<= 1) {
        for (int j = k >> 1; j > 0; j >>= 1) {
            for (int i = tid; i < P; i += 256) {
                int l = i ^ j;
                if (l > i) {
                    unsigned long long a = keys[i], d = keys[l];
                    bool sw = ((i & k) == 0) ? (a < d) : (a > d);
                    if (sw) { keys[i] = d; keys[l] = a; }
                }
            }
            __syncthreads();
        }
    }

    const int n_top = (cnt < TOPK) ? cnt : TOPK;

    // ---- Gather boxes for the top-200
    for (int k = tid; k < TOPK; k += 256) {
        if (k < n_top) {
            unsigned long long key = keys[k];
            int idx = (int)(~(unsigned int)(key & 0xffffffffull));
            float4 bb = ((const float4*)boxes)[(size_t)b * ROWS + idx];
            s_box4[k] = bb;
            s_area[k] = (bb.z - bb.x) * (bb.w - bb.y);
            s_sc[k]   = __uint_as_float((unsigned int)(key >> 32));
        } else {
            s_box4[k] = make_float4(0.f, 0.f, 0.f, 0.f);
            s_area[k] = 0.f; s_sc[k] = 0.f;
        }
    }
    __syncthreads();

    // ---- Suppression bitmask: thread i owns row i; inner j is a shared-mem
    //      broadcast (conflict-free). sup[i][w] bit jj: iou(i, w*32+jj) > 0.5, j > i.
    const int i = tid;
    if (i < n_top) {
        const float4 bi = s_box4[i];
        const float  ai = s_area[i];
        const int    w0 = i >> 5;
        #pragma unroll
        for (int w = 0; w < KW; w++) {
            unsigned int m = 0;
            if (w >= w0) {
                const int jend = (n_top - w * 32 < 32) ? (n_top - w * 32) : 32;
                #pragma unroll 8
                for (int jj = 0; jj < 32; jj++) {
                    if (jj >= jend) break;
                    int j = w * 32 + jj;
                    if (j > i) {
                        float4 bj = s_box4[j];
                        float xx1 = fmaxf(bi.x, bj.x);
                        float yy1 = fmaxf(bi.y, bj.y);
                        float xx2 = fminf(bi.z, bj.z);
                        float yy2 = fminf(bi.w, bj.w);
                        float inter = fmaxf(0.f, xx2 - xx1) * fmaxf(0.f, yy2 - yy1);
                        if (inter > 0.f) {
                            float un = (ai + s_area[j]) - inter;
                            if (inter / un > 0.5f) m |= (1u << jj);
                        }
                    }
                }
            }
            sup[i * KW + w] = m;
        }
    }
    __syncthreads();

    // ---- Serial greedy (thread 0, rem[] fully in registers via unrolled outer)
    if (tid == 0) {
        unsigned int rem[KW];
        #pragma unroll
        for (int w = 0; w < KW; w++) rem[w] = 0u;
        #pragma unroll
        for (int w0 = 0; w0 < KW; w0++) {
            int ibase = w0 * 32;
            for (int ii = 0; ii < 32; ii++) {
                int idx = ibase + ii;
                if (idx >= n_top) break;
                if (((rem[w0] >> ii) & 1u) == 0u) {
                    #pragma unroll
                    for (int w = 0; w < KW; w++) rem[w] |= sup[idx * KW + w];
                }
            }
        }
        #pragma unroll
        for (int w = 0; w < KW; w++) s_keepw[w] = ~rem[w];
    }
    __syncthreads();

    // ---- Write output: (b, c, k, 6) = [x1,y1,x2,y2,score,class] or zeros
    float* o = out + (size_t)bc * (TOPK * 6);
    const float cls = (float)c;
    for (int t = tid; t < TOPK * 6; t += 256) {
        int k = t / 6, f = t % 6;
        bool kp = (k < n_top) && (((s_keepw[k >> 5] >> (k & 31)) & 1u) != 0u);
        float v = 0.f;
        if (kp) {
            switch (f) {
                case 0: v = s_box4[k].x; break;
                case 1: v = s_box4[k].y; break;
                case 2: v = s_box4[k].z; break;
                case 3: v = s_box4[k].w; break;
                case 4: v = s_sc[k]; break;
                default: v = cls;   break;
            }
        }
        o[t] = v;
    }
}

// ---------------------------------------------------------------------------
extern "C" void kernel_launch(void* const* d_in, const int* in_sizes, int n_in,
                              void* d_out, int out_size) {
    const float* boxes  = (const float*)d_in[0];
    const float* scores = (const float*)d_in[1];
    if (n_in >= 2 && in_sizes[0] > in_sizes[1]) {  // scores is the bigger tensor
        boxes  = (const float*)d_in[1];
        scores = (const float*)d_in[0];
    }
    float* out = (float*)d_out;

    dim3 tgrid((ROWS + 31) / 32, (NCLS + 31) / 32, NBATCH);
    dim3 tblk(32, 8);
    transpose_kernel<<<tgrid, tblk>>>(scores);

    nms_kernel<<<NBATCH * NCLS, 256>>>(boxes, out);
}